// round 15
// baseline (speedup 1.0000x reference)
#include <cuda_runtime.h>
#include <cuda_bf16.h>
#include <cstdint>
#include <math.h>

// ---------------- problem constants ----------------
#define C_DIM   256
#define M_CLS   256
#define HW      16384
#define N_PIX   262144
#define TILE_P  64                     // pixels per GROUP-tile
#define KB      32                     // channels per A chunk
#define NKS     (C_DIM / KB)           // 8
#define NTASKS  (N_PIX / TILE_P)       // 4096
#define NTHREADS 512                   // 2 groups x 256
#define GRID     152                   // persistent: one CTA per SM
#define NGROUPS  (GRID * 2)            // 304 independent task streams
#define SCALE_EX2 20.60992915555662f   // (1/0.07) * log2(e)

// ---------------- smem layout (bytes) ----------------
#define SM_B       0
#define B_BYTES    (M_CLS * C_DIM * 2)     // 131072 (shared by both groups)
#define A_BUF      (TILE_P * 64)           // 4096 per buffer
#define SM_A_BASE  (B_BYTES)               // + g*8192 + buf*4096
#define SM_RED_B   (SM_A_BASE + 4 * A_BUF) // 147456; per group 2560B
#define SM_FIN     (SM_RED_B + 2 * 2560)   // 152576: final reduce scratch
#define SMEM_BYTES (SM_FIN + 3072 + 64)    // 155712

__device__ double g_sum[NGROUPS];
__device__ float  g_cnt[NGROUPS];
__device__ __align__(16) __nv_bfloat16 g_queue_bf[M_CLS * C_DIM];
__device__ unsigned int g_done;   // zero-init; reset by winning group each launch

__device__ __forceinline__ uint32_t smem_u32(const void* p) {
    uint32_t a;
    asm("{ .reg .u64 t; cvta.to.shared.u64 t, %1; cvt.u32.u64 %0, t; }" : "=r"(a) : "l"(p));
    return a;
}
__device__ __forceinline__ uint32_t pkbf2(float x, float y) {
    __nv_bfloat162 h = __floats2bfloat162_rn(x, y);
    return *(uint32_t*)&h;
}
__device__ __forceinline__ float ex2(float x) {
    float r;
    asm("ex2.approx.f32 %0, %1;" : "=f"(r) : "f"(x));
    return r;
}
__device__ __forceinline__ void prefetch_l2(const void* p) {
    asm volatile("prefetch.global.L2 [%0];" :: "l"(p));
}
#define BARG(id) asm volatile("bar.sync %0, 256;" :: "r"(id) : "memory")
#define CP_ASYNC16(dst, src) \
    asm volatile("cp.async.cg.shared.global [%0], [%1], 16;" :: "r"(dst), "l"(src) : "memory")
#define CP_COMMIT()  asm volatile("cp.async.commit_group;" ::: "memory")
#define CP_WAIT0()   asm volatile("cp.async.wait_group 0;" ::: "memory")

#define LDMATRIX_X4(r0, r1, r2, r3, addr) \
    asm volatile("ldmatrix.sync.aligned.m8n8.x4.shared.b16 {%0,%1,%2,%3}, [%4];" \
                 : "=r"(r0), "=r"(r1), "=r"(r2), "=r"(r3) : "r"(addr))

#define MMA16816(c, a0, a1, a2, a3, b0, b1) \
    asm volatile("mma.sync.aligned.m16n8k16.row.col.f32.bf16.bf16.f32 " \
                 "{%0,%1,%2,%3}, {%4,%5,%6,%7}, {%8,%9}, {%0,%1,%2,%3};" \
                 : "+f"((c)[0]), "+f"((c)[1]), "+f"((c)[2]), "+f"((c)[3]) \
                 : "r"(a0), "r"(a1), "r"(a2), "r"(a3), "r"(b0), "r"(b1))

// ---- pre-pass: queue f32 -> bf16 ----
__global__ void queue_to_bf16_kernel(const float* __restrict__ queue)
{
    int i = (blockIdx.x * blockDim.x + threadIdx.x) * 2;
    float2 v = *(const float2*)(queue + i);
    __nv_bfloat162 b;
    b.x = __float2bfloat16(v.x);
    b.y = __float2bfloat16(v.y);
    *(__nv_bfloat162*)(g_queue_bf + i) = b;
}

// ---- main: persistent; 2 independent 256-thread groups share one B tile ----
__global__ __launch_bounds__(NTHREADS, 1)
void pcl_main_kernel(const float* __restrict__ feats,
                     const int*   __restrict__ labels,
                     float*       __restrict__ out)
{
    extern __shared__ char smem[];
    __shared__ bool s_last[2];
    const uint32_t sb  = smem_u32(smem);
    const int tid  = threadIdx.x;
    const int g    = tid >> 8;          // group 0/1
    const int tig  = tid & 255;         // thread-in-group
    const int warp = tig >> 5;          // 0..7 within group
    const int lane = tid & 31;
    const int barid = 1 + g;

    // ---- B staging ONCE (whole CTA): 128KB, class-permuted + swizzled ----
    // Within each 64-class group: physical p6 = 16t + 2ni + e stored at logical
    // slot 8ni + 2t + e  ->  a thread's 16 epilogue classes are contiguous.
    {
        #pragma unroll
        for (int i = 0; i < 16; i++) {
            int q    = tid + NTHREADS * i;       // 0..8191 16B-chunks
            int cls  = q >> 5;                   // physical class
            int c    = q & 31;
            int p6   = cls & 63;
            int slot = (((p6 >> 1) & 7) << 3) | (((p6 >> 4) & 3) << 1) | (p6 & 1);
            int lrow = (cls & ~63) | slot;       // logical smem row
            uint32_t dst = sb + SM_B + lrow * 512 + ((c ^ (lrow & 7)) << 4);
            const void* src = (const char*)g_queue_bf + cls * 512 + c * 16;
            CP_ASYNC16(dst, src);
        }
        CP_COMMIT();
    }

    // ---- A staging roles (within group): pix = tig&63, cq = tig>>6 (8 ch) ----
    const int pixA = tig & 63;
    const int cq   = tig >> 6;
    const uint32_t a_st_off = pixA * 64 + ((cq ^ ((pixA >> 1) & 3)) << 4);
    const uint32_t smA[2] = { sb + SM_A_BASE + (uint32_t)g * 2 * A_BUF,
                              sb + SM_A_BASE + (uint32_t)g * 2 * A_BUF + A_BUF };

    float areg[8];
    auto loadA = [&](const float* fb, int ks) {
        #pragma unroll
        for (int j = 0; j < 8; j++)
            areg[j] = __ldg(fb + (size_t)(ks * KB + cq * 8 + j) * HW + pixA);
    };
    auto storeA = [&](uint32_t abase) {
        uint4 w;
        w.x = pkbf2(areg[0], areg[1]);
        w.y = pkbf2(areg[2], areg[3]);
        w.z = pkbf2(areg[4], areg[5]);
        w.w = pkbf2(areg[6], areg[7]);
        asm volatile("st.shared.v4.b32 [%0], {%1,%2,%3,%4};"
                     :: "r"(abase + a_st_off), "r"(w.x), "r"(w.y), "r"(w.z), "r"(w.w) : "memory");
    };

    // ---- warp tiling per group: 8 warps = 2(pix) x 4(cls); tile 32x64 ----
    const int wm = warp & 1;
    const int wn = warp >> 1;

    const int arow0 = wm * 32 + (lane & 15);
    const int ksel  = lane >> 4;
    const uint32_t a_ld_base[2] = { (uint32_t)(arow0 * 64),
                                    (uint32_t)((arow0 + 16) * 64) };
    const uint32_t a_swz[2] = { (uint32_t)((arow0 >> 1) & 3),
                                (uint32_t)(((arow0 + 16) >> 1) & 3) };

    const int bg   = lane & 7;
    const int bsel = lane >> 3;
    const int bofs = bg + ((bsel >= 2) ? 8 : 0);
    const int bkh  = bsel & 1;

    const int gq = lane >> 2;
    const int t  = lane & 3;
    float* red_sn = (float*)(smem + SM_RED_B + g * 2560);          // [4][64]
    float* red_sp = (float*)(smem + SM_RED_B + g * 2560 + 1024);   // [4][64]
    float* wpart  = (float*)(smem + SM_RED_B + g * 2560 + 2048);   // [4]

    double acc_s = 0.0;
    float  acc_c = 0.0f;

    // ---- prologue for first task ----
    const int gid = blockIdx.x * 2 + g;
    int task = gid;
    const float* fbase = feats + (size_t)((task * TILE_P) / HW) * C_DIM * HW
                               + ((task * TILE_P) % HW);
    loadA(fbase, 0);
    storeA(smA[0]);
    CP_WAIT0();
    __syncthreads();   // B visible + both groups' first A staged; last CTA-wide sync

    // ---- persistent task loop (group-independent from here on) ----
    #pragma unroll 1
    for (; task < NTASKS; task += NGROUPS) {
        const int pix0 = task * TILE_P;
        const int next_task = task + NGROUPS;
        const float* fbase_next =
            (next_task < NTASKS)
                ? feats + (size_t)((next_task * TILE_P) / HW) * C_DIM * HW
                        + ((next_task * TILE_P) % HW)
                : fbase;

        // L2-prefetch this tile's label lines (no registers held, no ordering
        // semantics — purely a cache hint; epilogue loads then hit L2)
        #pragma unroll
        for (int mi = 0; mi < 2; mi++)
            #pragma unroll
            for (int h = 0; h < 2; h++) {
                const int pixel = wm * 32 + mi * 16 + h * 8 + gq;
                prefetch_l2(labels + (size_t)(pix0 + pixel) * M_CLS + wn * 64 + t * 16);
            }

        float acc[2][8][4];
        #pragma unroll
        for (int mi = 0; mi < 2; mi++)
            #pragma unroll
            for (int ni = 0; ni < 8; ni++)
                #pragma unroll
                for (int r = 0; r < 4; r++) acc[mi][ni][r] = 0.0f;

        // ---- mainloop: 8 chunks, double-buffered A (barrier EVERY chunk:
        //      required RAW guard — see R14 post-mortem), cross-task prefetch ----
        #pragma unroll 1
        for (int ks = 0; ks < NKS; ks++) {
            const bool have_next = (ks < NKS - 1) || (next_task < NTASKS);
            if (ks < NKS - 1)           loadA(fbase, ks + 1);
            else if (have_next)         loadA(fbase_next, 0);

            const uint32_t acur = smA[ks & 1];
            #pragma unroll
            for (int kf = 0; kf < 2; kf++) {
                uint32_t afr[2][4];
                #pragma unroll
                for (int mi = 0; mi < 2; mi++) {
                    uint32_t addr = acur + a_ld_base[mi] +
                                    (((uint32_t)(kf * 2 + ksel) ^ a_swz[mi]) << 4);
                    LDMATRIX_X4(afr[mi][0], afr[mi][1], afr[mi][2], afr[mi][3], addr);
                }
                const uint32_t kchunk = ks * 4 + kf * 2 + bkh;
                #pragma unroll
                for (int nt = 0; nt < 4; nt++) {
                    const int lcls = wn * 64 + nt * 16 + bofs;
                    uint32_t b0, b1, b2, b3;
                    uint32_t addr = sb + SM_B + lcls * 512 +
                                    ((kchunk ^ (uint32_t)(lcls & 7)) << 4);
                    LDMATRIX_X4(b0, b1, b2, b3, addr);
                    #pragma unroll
                    for (int mi = 0; mi < 2; mi++) {
                        MMA16816(acc[mi][nt * 2 + 0], afr[mi][0], afr[mi][1], afr[mi][2], afr[mi][3], b0, b1);
                        MMA16816(acc[mi][nt * 2 + 1], afr[mi][0], afr[mi][1], afr[mi][2], afr[mi][3], b2, b3);
                    }
                }
            }

            if (have_next) {
                storeA(smA[(ks + 1) & 1]);
                BARG(barid);
            }
        }

        // ---- register epilogue: acc[mi][ni][h*2+e] <-> class wn*64+16t+2ni+e ----
        #pragma unroll
        for (int mi = 0; mi < 2; mi++) {
            #pragma unroll
            for (int h = 0; h < 2; h++) {
                const int pixel = wm * 32 + mi * 16 + h * 8 + gq;
                const int4* lp = (const int4*)(labels +
                    (size_t)(pix0 + pixel) * M_CLS + wn * 64 + t * 16);
                int4 l0 = __ldg(lp);
                int4 l1 = __ldg(lp + 1);
                int4 l2 = __ldg(lp + 2);
                int4 l3 = __ldg(lp + 3);
                int l[16] = { l0.x, l0.y, l0.z, l0.w, l1.x, l1.y, l1.z, l1.w,
                              l2.x, l2.y, l2.z, l2.w, l3.x, l3.y, l3.z, l3.w };
                float sn = 0.0f, sp = 0.0f;
                #pragma unroll
                for (int ni = 0; ni < 8; ni++) {
                    #pragma unroll
                    for (int e = 0; e < 2; e++) {
                        int   lv = l[2 * ni + e];
                        float v  = acc[mi][ni][h * 2 + e] * SCALE_EX2;
                        float ev = ex2(lv ? -v : v);
                        if (lv) sp += ev; else sn += ev;
                    }
                }
                sn += __shfl_xor_sync(0xFFFFFFFFu, sn, 1);
                sn += __shfl_xor_sync(0xFFFFFFFFu, sn, 2);
                sp += __shfl_xor_sync(0xFFFFFFFFu, sp, 1);
                sp += __shfl_xor_sync(0xFFFFFFFFu, sp, 2);
                if (t == 0) {
                    red_sn[wn * 64 + pixel] = sn;
                    red_sp[wn * 64 + pixel] = sp;
                }
            }
        }
        BARG(barid);

        float th_loss = 0.0f, th_cnt = 0.0f;
        if (tig < 64) {    // warps 0 and 1 of the group (fully convergent)
            float tsn = red_sn[tig] + red_sn[64 + tig] + red_sn[128 + tig] + red_sn[192 + tig];
            float tsp = red_sp[tig] + red_sp[64 + tig] + red_sp[128 + tig] + red_sp[192 + tig];
            float loss = logf(tsn * tsp + 1.0f);
            th_loss = loss;
            th_cnt  = (loss != 0.0f) ? 1.0f : 0.0f;
            #pragma unroll
            for (int o = 16; o > 0; o >>= 1) {
                th_loss += __shfl_xor_sync(0xFFFFFFFFu, th_loss, o);
                th_cnt  += __shfl_xor_sync(0xFFFFFFFFu, th_cnt,  o);
            }
            if (lane == 0) { wpart[(tig >> 5) * 2] = th_loss; wpart[(tig >> 5) * 2 + 1] = th_cnt; }
        }
        BARG(barid);
        if (tig == 0) {
            acc_s += (double)(wpart[0] + wpart[2]);
            acc_c += wpart[1] + wpart[3];
        }

        fbase = fbase_next;
    }

    // ---- publish per-group totals; last finishing group reduces ----
    if (tig == 0) {
        g_sum[gid] = acc_s;
        g_cnt[gid] = acc_c;
        __threadfence();
        unsigned old = atomicAdd(&g_done, 1u);
        s_last[g] = (old == NGROUPS - 1);
    }
    BARG(barid);

    if (s_last[g]) {
        double* dsum = (double*)(smem + SM_FIN);          // 256 doubles
        float*  fcnt = (float*)(smem + SM_FIN + 2048);    // 256 floats
        double s = 0.0;
        float  c = 0.0f;
        #pragma unroll 1
        for (int i = tig; i < NGROUPS; i += 256) { s += g_sum[i]; c += g_cnt[i]; }
        dsum[tig] = s;
        fcnt[tig] = c;
        BARG(barid);
        for (int o = 128; o > 0; o >>= 1) {
            if (tig < o) { dsum[tig] += dsum[tig + o]; fcnt[tig] += fcnt[tig + o]; }
            BARG(barid);
        }
        if (tig == 0) {
            float cnt = fcnt[0];
            out[0] = (cnt == 0.0f) ? 0.0f : (float)(dsum[0] / (double)fmaxf(cnt, 1.0f));
            __threadfence();
            g_done = 0;   // reset for graph replay
        }
    }
}

extern "C" void kernel_launch(void* const* d_in, const int* in_sizes, int n_in,
                              void* d_out, int out_size)
{
    // metadata.txt order: feats (f32), queue (f32), labels (i32).
    // feats and labels have identical element counts — positional ID only.
    const float* feats  = (const float*)d_in[0];
    const float* queue  = (const float*)d_in[1];
    const int*   labels = (const int*)d_in[2];

    cudaFuncSetAttribute(pcl_main_kernel,
                         cudaFuncAttributeMaxDynamicSharedMemorySize, SMEM_BYTES);

    queue_to_bf16_kernel<<<M_CLS * C_DIM / (2 * 256), 256>>>(queue);
    pcl_main_kernel<<<GRID, NTHREADS, SMEM_BYTES>>>(feats, labels, (float*)d_out);
}

// round 16
// speedup vs baseline: 1.0775x; 1.0775x over previous
#include <cuda_runtime.h>
#include <cuda_bf16.h>
#include <cstdint>
#include <math.h>

// ---------------- problem constants ----------------
#define C_DIM   256
#define M_CLS   256
#define HW      16384
#define N_PIX   262144
#define TILE_P  64                     // pixels per GROUP-tile
#define KB      32                     // channels per A chunk
#define NKS     (C_DIM / KB)           // 8
#define NTASKS  (N_PIX / TILE_P)       // 4096
#define NTHREADS 512                   // 2 groups x 256
#define GRID     152                   // persistent: one CTA per SM
#define NGROUPS  (GRID * 2)            // 304 independent task streams
#define SCALE_EX2 20.60992915555662f   // (1/0.07) * log2(e)

// ---------------- smem layout (bytes) ----------------
#define SM_B       0
#define B_BYTES    (M_CLS * C_DIM * 2)     // 131072 (shared by both groups)
#define A_BUF      (TILE_P * 64)           // 4096 per buffer
#define SM_A_BASE  (B_BYTES)               // + g*8192 + buf*4096
#define SM_RED_B   (SM_A_BASE + 4 * A_BUF) // 147456; per group 2560B
#define SM_FIN     (SM_RED_B + 2 * 2560)   // 152576: final reduce scratch
#define SMEM_BYTES (SM_FIN + 3072 + 64)    // 155712

__device__ double g_sum[NGROUPS];
__device__ float  g_cnt[NGROUPS];
__device__ unsigned int g_done;   // zero-init; reset by winning group each launch

__device__ __forceinline__ uint32_t smem_u32(const void* p) {
    uint32_t a;
    asm("{ .reg .u64 t; cvta.to.shared.u64 t, %1; cvt.u32.u64 %0, t; }" : "=r"(a) : "l"(p));
    return a;
}
__device__ __forceinline__ uint32_t pkbf2(float x, float y) {
    __nv_bfloat162 h = __floats2bfloat162_rn(x, y);
    return *(uint32_t*)&h;
}
__device__ __forceinline__ float ex2(float x) {
    float r;
    asm("ex2.approx.f32 %0, %1;" : "=f"(r) : "f"(x));
    return r;
}
#define BARG(id) asm volatile("bar.sync %0, 256;" :: "r"(id) : "memory")

#define LDMATRIX_X4(r0, r1, r2, r3, addr) \
    asm volatile("ldmatrix.sync.aligned.m8n8.x4.shared.b16 {%0,%1,%2,%3}, [%4];" \
                 : "=r"(r0), "=r"(r1), "=r"(r2), "=r"(r3) : "r"(addr))

#define MMA16816(c, a0, a1, a2, a3, b0, b1) \
    asm volatile("mma.sync.aligned.m16n8k16.row.col.f32.bf16.bf16.f32 " \
                 "{%0,%1,%2,%3}, {%4,%5,%6,%7}, {%8,%9}, {%0,%1,%2,%3};" \
                 : "+f"((c)[0]), "+f"((c)[1]), "+f"((c)[2]), "+f"((c)[3]) \
                 : "r"(a0), "r"(a1), "r"(a2), "r"(a3), "r"(b0), "r"(b1))

// ---- main: persistent; 2 independent 256-thread groups share one B tile ----
__global__ __launch_bounds__(NTHREADS, 1)
void pcl_main_kernel(const float* __restrict__ feats,
                     const float* __restrict__ queue,
                     const int*   __restrict__ labels,
                     float*       __restrict__ out)
{
    extern __shared__ char smem[];
    __shared__ bool s_last[2];
    const uint32_t sb  = smem_u32(smem);
    const int tid  = threadIdx.x;
    const int g    = tid >> 8;          // group 0/1
    const int tig  = tid & 255;         // thread-in-group
    const int warp = tig >> 5;          // 0..7 within group
    const int lane = tid & 31;
    const int barid = 1 + g;

    // ---- B staging ONCE (whole CTA): f32 queue -> bf16, class-permuted +
    //      swizzled, directly in the prologue (no separate prepass kernel).
    // Within each 64-class group: physical p6 = 16t + 2ni + e stored at logical
    // slot 8ni + 2t + e  ->  a thread's 16 epilogue classes are contiguous.
    {
        #pragma unroll
        for (int i = 0; i < 16; i++) {
            int q    = tid + NTHREADS * i;       // 0..8191 16B-bf16-chunks
            int cls  = q >> 5;                   // physical class
            int c    = q & 31;                   // 8-channel chunk within class
            int p6   = cls & 63;
            int slot = (((p6 >> 1) & 7) << 3) | (((p6 >> 4) & 3) << 1) | (p6 & 1);
            int lrow = (cls & ~63) | slot;       // logical smem row
            uint32_t dst = sb + SM_B + lrow * 512 + ((c ^ (lrow & 7)) << 4);
            const float4* src = (const float4*)(queue + cls * C_DIM + c * 8);
            float4 v0 = __ldg(src);
            float4 v1 = __ldg(src + 1);
            uint4 w;
            w.x = pkbf2(v0.x, v0.y);
            w.y = pkbf2(v0.z, v0.w);
            w.z = pkbf2(v1.x, v1.y);
            w.w = pkbf2(v1.z, v1.w);
            asm volatile("st.shared.v4.b32 [%0], {%1,%2,%3,%4};"
                         :: "r"(dst), "r"(w.x), "r"(w.y), "r"(w.z), "r"(w.w) : "memory");
        }
    }

    // ---- A staging roles (within group): pix = tig&63, cq = tig>>6 (8 ch) ----
    const int pixA = tig & 63;
    const int cq   = tig >> 6;
    const uint32_t a_st_off = pixA * 64 + ((cq ^ ((pixA >> 1) & 3)) << 4);
    const uint32_t smA[2] = { sb + SM_A_BASE + (uint32_t)g * 2 * A_BUF,
                              sb + SM_A_BASE + (uint32_t)g * 2 * A_BUF + A_BUF };

    float areg[8];
    auto loadA = [&](const float* fb, int ks) {
        #pragma unroll
        for (int j = 0; j < 8; j++)
            areg[j] = __ldg(fb + (size_t)(ks * KB + cq * 8 + j) * HW + pixA);
    };
    auto storeA = [&](uint32_t abase) {
        uint4 w;
        w.x = pkbf2(areg[0], areg[1]);
        w.y = pkbf2(areg[2], areg[3]);
        w.z = pkbf2(areg[4], areg[5]);
        w.w = pkbf2(areg[6], areg[7]);
        asm volatile("st.shared.v4.b32 [%0], {%1,%2,%3,%4};"
                     :: "r"(abase + a_st_off), "r"(w.x), "r"(w.y), "r"(w.z), "r"(w.w) : "memory");
    };

    // ---- warp tiling per group: 8 warps = 2(pix) x 4(cls); tile 32x64 ----
    const int wm = warp & 1;
    const int wn = warp >> 1;

    const int arow0 = wm * 32 + (lane & 15);
    const int ksel  = lane >> 4;
    const uint32_t a_ld_base[2] = { (uint32_t)(arow0 * 64),
                                    (uint32_t)((arow0 + 16) * 64) };
    const uint32_t a_swz[2] = { (uint32_t)((arow0 >> 1) & 3),
                                (uint32_t)(((arow0 + 16) >> 1) & 3) };

    const int bg   = lane & 7;
    const int bsel = lane >> 3;
    const int bofs = bg + ((bsel >= 2) ? 8 : 0);
    const int bkh  = bsel & 1;

    const int gq = lane >> 2;
    const int t  = lane & 3;
    float* red_sn = (float*)(smem + SM_RED_B + g * 2560);          // [4][64]
    float* red_sp = (float*)(smem + SM_RED_B + g * 2560 + 1024);   // [4][64]
    float* wpart  = (float*)(smem + SM_RED_B + g * 2560 + 2048);   // [4]

    double acc_s = 0.0;
    float  acc_c = 0.0f;

    // ---- prologue for first task ----
    const int gid = blockIdx.x * 2 + g;
    int task = gid;
    const float* fbase = feats + (size_t)((task * TILE_P) / HW) * C_DIM * HW
                               + ((task * TILE_P) % HW);
    loadA(fbase, 0);
    storeA(smA[0]);
    __syncthreads();   // B visible + both groups' first A staged; last CTA-wide sync

    // ---- persistent task loop (group-independent from here on) ----
    #pragma unroll 1
    for (; task < NTASKS; task += NGROUPS) {
        const int pix0 = task * TILE_P;
        const int next_task = task + NGROUPS;
        const float* fbase_next =
            (next_task < NTASKS)
                ? feats + (size_t)((next_task * TILE_P) / HW) * C_DIM * HW
                        + ((next_task * TILE_P) % HW)
                : fbase;

        float acc[2][8][4];
        #pragma unroll
        for (int mi = 0; mi < 2; mi++)
            #pragma unroll
            for (int ni = 0; ni < 8; ni++)
                #pragma unroll
                for (int r = 0; r < 4; r++) acc[mi][ni][r] = 0.0f;

        // ---- mainloop: 8 chunks, double-buffered A (barrier EVERY chunk:
        //      required RAW guard — see R14 post-mortem), cross-task prefetch ----
        #pragma unroll 1
        for (int ks = 0; ks < NKS; ks++) {
            const bool have_next = (ks < NKS - 1) || (next_task < NTASKS);
            if (ks < NKS - 1)           loadA(fbase, ks + 1);
            else if (have_next)         loadA(fbase_next, 0);

            const uint32_t acur = smA[ks & 1];
            #pragma unroll
            for (int kf = 0; kf < 2; kf++) {
                uint32_t afr[2][4];
                #pragma unroll
                for (int mi = 0; mi < 2; mi++) {
                    uint32_t addr = acur + a_ld_base[mi] +
                                    (((uint32_t)(kf * 2 + ksel) ^ a_swz[mi]) << 4);
                    LDMATRIX_X4(afr[mi][0], afr[mi][1], afr[mi][2], afr[mi][3], addr);
                }
                const uint32_t kchunk = ks * 4 + kf * 2 + bkh;
                #pragma unroll
                for (int nt = 0; nt < 4; nt++) {
                    const int lcls = wn * 64 + nt * 16 + bofs;
                    uint32_t b0, b1, b2, b3;
                    uint32_t addr = sb + SM_B + lcls * 512 +
                                    ((kchunk ^ (uint32_t)(lcls & 7)) << 4);
                    LDMATRIX_X4(b0, b1, b2, b3, addr);
                    #pragma unroll
                    for (int mi = 0; mi < 2; mi++) {
                        MMA16816(acc[mi][nt * 2 + 0], afr[mi][0], afr[mi][1], afr[mi][2], afr[mi][3], b0, b1);
                        MMA16816(acc[mi][nt * 2 + 1], afr[mi][0], afr[mi][1], afr[mi][2], afr[mi][3], b2, b3);
                    }
                }
            }

            if (have_next) {
                storeA(smA[(ks + 1) & 1]);
                BARG(barid);
            }
        }

        // ---- register epilogue: acc[mi][ni][h*2+e] <-> class wn*64+16t+2ni+e ----
        #pragma unroll
        for (int mi = 0; mi < 2; mi++) {
            #pragma unroll
            for (int h = 0; h < 2; h++) {
                const int pixel = wm * 32 + mi * 16 + h * 8 + gq;
                const int4* lp = (const int4*)(labels +
                    (size_t)(pix0 + pixel) * M_CLS + wn * 64 + t * 16);
                int4 l0 = __ldg(lp);
                int4 l1 = __ldg(lp + 1);
                int4 l2 = __ldg(lp + 2);
                int4 l3 = __ldg(lp + 3);
                int l[16] = { l0.x, l0.y, l0.z, l0.w, l1.x, l1.y, l1.z, l1.w,
                              l2.x, l2.y, l2.z, l2.w, l3.x, l3.y, l3.z, l3.w };
                float sn = 0.0f, sp = 0.0f;
                #pragma unroll
                for (int ni = 0; ni < 8; ni++) {
                    #pragma unroll
                    for (int e = 0; e < 2; e++) {
                        int   lv = l[2 * ni + e];
                        float v  = acc[mi][ni][h * 2 + e] * SCALE_EX2;
                        float ev = ex2(lv ? -v : v);
                        if (lv) sp += ev; else sn += ev;
                    }
                }
                sn += __shfl_xor_sync(0xFFFFFFFFu, sn, 1);
                sn += __shfl_xor_sync(0xFFFFFFFFu, sn, 2);
                sp += __shfl_xor_sync(0xFFFFFFFFu, sp, 1);
                sp += __shfl_xor_sync(0xFFFFFFFFu, sp, 2);
                if (t == 0) {
                    red_sn[wn * 64 + pixel] = sn;
                    red_sp[wn * 64 + pixel] = sp;
                }
            }
        }
        BARG(barid);

        float th_loss = 0.0f, th_cnt = 0.0f;
        if (tig < 64) {    // warps 0 and 1 of the group (fully convergent)
            float tsn = red_sn[tig] + red_sn[64 + tig] + red_sn[128 + tig] + red_sn[192 + tig];
            float tsp = red_sp[tig] + red_sp[64 + tig] + red_sp[128 + tig] + red_sp[192 + tig];
            float loss = logf(tsn * tsp + 1.0f);
            th_loss = loss;
            th_cnt  = (loss != 0.0f) ? 1.0f : 0.0f;
            #pragma unroll
            for (int o = 16; o > 0; o >>= 1) {
                th_loss += __shfl_xor_sync(0xFFFFFFFFu, th_loss, o);
                th_cnt  += __shfl_xor_sync(0xFFFFFFFFu, th_cnt,  o);
            }
            if (lane == 0) { wpart[(tig >> 5) * 2] = th_loss; wpart[(tig >> 5) * 2 + 1] = th_cnt; }
        }
        BARG(barid);
        if (tig == 0) {
            acc_s += (double)(wpart[0] + wpart[2]);
            acc_c += wpart[1] + wpart[3];
        }

        fbase = fbase_next;
    }

    // ---- publish per-group totals; last finishing group reduces ----
    if (tig == 0) {
        g_sum[gid] = acc_s;
        g_cnt[gid] = acc_c;
        __threadfence();
        unsigned old = atomicAdd(&g_done, 1u);
        s_last[g] = (old == NGROUPS - 1);
    }
    BARG(barid);

    if (s_last[g]) {
        double* dsum = (double*)(smem + SM_FIN);          // 256 doubles
        float*  fcnt = (float*)(smem + SM_FIN + 2048);    // 256 floats
        double s = 0.0;
        float  c = 0.0f;
        #pragma unroll 1
        for (int i = tig; i < NGROUPS; i += 256) { s += g_sum[i]; c += g_cnt[i]; }
        dsum[tig] = s;
        fcnt[tig] = c;
        BARG(barid);
        for (int o = 128; o > 0; o >>= 1) {
            if (tig < o) { dsum[tig] += dsum[tig + o]; fcnt[tig] += fcnt[tig + o]; }
            BARG(barid);
        }
        if (tig == 0) {
            float cnt = fcnt[0];
            out[0] = (cnt == 0.0f) ? 0.0f : (float)(dsum[0] / (double)fmaxf(cnt, 1.0f));
            __threadfence();
            g_done = 0;   // reset for graph replay
        }
    }
}

extern "C" void kernel_launch(void* const* d_in, const int* in_sizes, int n_in,
                              void* d_out, int out_size)
{
    // metadata.txt order: feats (f32), queue (f32), labels (i32).
    // feats and labels have identical element counts — positional ID only.
    const float* feats  = (const float*)d_in[0];
    const float* queue  = (const float*)d_in[1];
    const int*   labels = (const int*)d_in[2];

    cudaFuncSetAttribute(pcl_main_kernel,
                         cudaFuncAttributeMaxDynamicSharedMemorySize, SMEM_BYTES);

    pcl_main_kernel<<<GRID, NTHREADS, SMEM_BYTES>>>(feats, queue, labels, (float*)d_out);
}

// round 17
// speedup vs baseline: 1.1202x; 1.0397x over previous
#include <cuda_runtime.h>
#include <cuda_bf16.h>
#include <cstdint>
#include <math.h>

// ---------------- problem constants ----------------
#define C_DIM   256
#define M_CLS   256
#define HW      16384
#define N_PIX   262144
#define TILE_P  32                     // pixels per GROUP-tile
#define KB      32                     // channels per A chunk
#define NKS     (C_DIM / KB)           // 8
#define NTASKS  (N_PIX / TILE_P)       // 8192
#define NTHREADS 512                   // 4 groups x 128
#define GRID     152                   // persistent: one CTA per SM
#define NGROUPS  (GRID * 4)            // 608 independent task streams
#define SCALE_EX2 20.60992915555662f   // (1/0.07) * log2(e)

// ---------------- smem layout (bytes) ----------------
#define SM_B       0
#define B_BYTES    (M_CLS * C_DIM * 2)     // 131072 (shared by all 4 groups)
#define A_BUF      (TILE_P * 64)           // 2048 per buffer (32px x 32ch bf16)
#define SM_A_BASE  (B_BYTES)               // + g*4096 + buf*2048 (2 buffers/group)
#define SM_RED_B   (SM_A_BASE + 8 * A_BUF) // 147456; per group 1152B: sn[128],sp[128],wpart
#define SM_FIN     (SM_RED_B + 4 * 1152)   // 152064: final reduce scratch
#define SMEM_BYTES (SM_FIN + 1536 + 64)    // 153664

__device__ double g_sum[NGROUPS];
__device__ float  g_cnt[NGROUPS];
__device__ unsigned int g_done;   // zero-init; reset by winning group each launch

__device__ __forceinline__ uint32_t smem_u32(const void* p) {
    uint32_t a;
    asm("{ .reg .u64 t; cvta.to.shared.u64 t, %1; cvt.u32.u64 %0, t; }" : "=r"(a) : "l"(p));
    return a;
}
__device__ __forceinline__ uint32_t pkbf2(float x, float y) {
    __nv_bfloat162 h = __floats2bfloat162_rn(x, y);
    return *(uint32_t*)&h;
}
__device__ __forceinline__ float ex2(float x) {
    float r;
    asm("ex2.approx.f32 %0, %1;" : "=f"(r) : "f"(x));
    return r;
}
#define BARG(id) asm volatile("bar.sync %0, 128;" :: "r"(id) : "memory")

#define LDMATRIX_X4(r0, r1, r2, r3, addr) \
    asm volatile("ldmatrix.sync.aligned.m8n8.x4.shared.b16 {%0,%1,%2,%3}, [%4];" \
                 : "=r"(r0), "=r"(r1), "=r"(r2), "=r"(r3) : "r"(addr))

#define MMA16816(c, a0, a1, a2, a3, b0, b1) \
    asm volatile("mma.sync.aligned.m16n8k16.row.col.f32.bf16.bf16.f32 " \
                 "{%0,%1,%2,%3}, {%4,%5,%6,%7}, {%8,%9}, {%0,%1,%2,%3};" \
                 : "+f"((c)[0]), "+f"((c)[1]), "+f"((c)[2]), "+f"((c)[3]) \
                 : "r"(a0), "r"(a1), "r"(a2), "r"(a3), "r"(b0), "r"(b1))

// ---- main: persistent; 4 independent 128-thread groups share one B tile ----
__global__ __launch_bounds__(NTHREADS, 1)
void pcl_main_kernel(const float* __restrict__ feats,
                     const float* __restrict__ queue,
                     const int*   __restrict__ labels,
                     float*       __restrict__ out)
{
    extern __shared__ char smem[];
    __shared__ bool s_last[4];
    const uint32_t sb  = smem_u32(smem);
    const int tid  = threadIdx.x;
    const int g    = tid >> 7;          // group 0..3
    const int tig  = tid & 127;         // thread-in-group
    const int warp = tig >> 5;          // 0..3 within group
    const int lane = tid & 31;
    const int barid = 1 + g;

    // ---- B staging ONCE (whole CTA): f32 queue -> bf16, class-permuted +
    //      swizzled, in the prologue. Within each 64-class group: physical
    //      p6 = 16t + 2ni + e stored at logical slot 8ni + 2t + e  ->  a
    //      thread's 16 epilogue classes are contiguous (4 int4 label loads).
    {
        #pragma unroll
        for (int i = 0; i < 16; i++) {
            int q    = tid + NTHREADS * i;       // 0..8191 16B-bf16-chunks
            int cls  = q >> 5;                   // physical class
            int c    = q & 31;                   // 8-channel chunk within class
            int p6   = cls & 63;
            int slot = (((p6 >> 1) & 7) << 3) | (((p6 >> 4) & 3) << 1) | (p6 & 1);
            int lrow = (cls & ~63) | slot;       // logical smem row
            uint32_t dst = sb + SM_B + lrow * 512 + ((c ^ (lrow & 7)) << 4);
            const float4* src = (const float4*)(queue + cls * C_DIM + c * 8);
            float4 v0 = __ldg(src);
            float4 v1 = __ldg(src + 1);
            uint4 w;
            w.x = pkbf2(v0.x, v0.y);
            w.y = pkbf2(v0.z, v0.w);
            w.z = pkbf2(v1.x, v1.y);
            w.w = pkbf2(v1.z, v1.w);
            asm volatile("st.shared.v4.b32 [%0], {%1,%2,%3,%4};"
                         :: "r"(dst), "r"(w.x), "r"(w.y), "r"(w.z), "r"(w.w) : "memory");
        }
    }

    // ---- A staging roles (within group): pix = tig&31, cq = tig>>5 (8 ch) ----
    const int pixA = tig & 31;
    const int cq   = tig >> 5;          // 0..3: channels cq*8 .. +7
    const uint32_t a_st_off = pixA * 64 + ((cq ^ ((pixA >> 1) & 3)) << 4);
    const uint32_t smA[2] = { sb + SM_A_BASE + (uint32_t)g * 2 * A_BUF,
                              sb + SM_A_BASE + (uint32_t)g * 2 * A_BUF + A_BUF };

    float areg[8];
    auto loadA = [&](const float* fb, int ks) {
        #pragma unroll
        for (int j = 0; j < 8; j++)
            areg[j] = __ldg(fb + (size_t)(ks * KB + cq * 8 + j) * HW + pixA);
    };
    auto storeA = [&](uint32_t abase) {
        uint4 w;
        w.x = pkbf2(areg[0], areg[1]);
        w.y = pkbf2(areg[2], areg[3]);
        w.z = pkbf2(areg[4], areg[5]);
        w.w = pkbf2(areg[6], areg[7]);
        asm volatile("st.shared.v4.b32 [%0], {%1,%2,%3,%4};"
                     :: "r"(abase + a_st_off), "r"(w.x), "r"(w.y), "r"(w.z), "r"(w.w) : "memory");
    };

    // ---- warp tiling per group: 4 warps = 1(pix) x 4(cls); tile 32x64 ----
    const int wn = warp;                 // class coord -> cols wn*64..+63

    const int arow0 = lane & 15;
    const int ksel  = lane >> 4;
    const uint32_t a_ld_base[2] = { (uint32_t)(arow0 * 64),
                                    (uint32_t)((arow0 + 16) * 64) };
    const uint32_t a_swz[2] = { (uint32_t)((arow0 >> 1) & 3),
                                (uint32_t)(((arow0 + 16) >> 1) & 3) };

    const int bg   = lane & 7;
    const int bsel = lane >> 3;
    const int bofs = bg + ((bsel >= 2) ? 8 : 0);
    const int bkh  = bsel & 1;

    const int gq = lane >> 2;
    const int t  = lane & 3;
    float* red_sn = (float*)(smem + SM_RED_B + g * 1152);          // [4][32]
    float* red_sp = (float*)(smem + SM_RED_B + g * 1152 + 512);    // [4][32]
    float* wpart  = (float*)(smem + SM_RED_B + g * 1152 + 1024);   // [2]

    double acc_s = 0.0;
    float  acc_c = 0.0f;

    // ---- prologue for first task ----
    const int gid = blockIdx.x * 4 + g;
    int task = gid;
    const float* fbase = feats + (size_t)((task * TILE_P) / HW) * C_DIM * HW
                               + ((task * TILE_P) % HW);
    loadA(fbase, 0);
    storeA(smA[0]);
    __syncthreads();   // B visible + all groups' first A staged; last CTA-wide sync

    // ---- persistent task loop (group-independent from here on) ----
    #pragma unroll 1
    for (; task < NTASKS; task += NGROUPS) {
        const int pix0 = task * TILE_P;
        const int next_task = task + NGROUPS;
        const float* fbase_next =
            (next_task < NTASKS)
                ? feats + (size_t)((next_task * TILE_P) / HW) * C_DIM * HW
                        + ((next_task * TILE_P) % HW)
                : fbase;

        float acc[2][8][4];
        #pragma unroll
        for (int mi = 0; mi < 2; mi++)
            #pragma unroll
            for (int ni = 0; ni < 8; ni++)
                #pragma unroll
                for (int r = 0; r < 4; r++) acc[mi][ni][r] = 0.0f;

        // ---- mainloop: 8 chunks, double-buffered A (barrier EVERY chunk:
        //      required RAW guard), cross-task prefetch ----
        #pragma unroll 1
        for (int ks = 0; ks < NKS; ks++) {
            const bool have_next = (ks < NKS - 1) || (next_task < NTASKS);
            if (ks < NKS - 1)           loadA(fbase, ks + 1);
            else if (have_next)         loadA(fbase_next, 0);

            const uint32_t acur = smA[ks & 1];
            #pragma unroll
            for (int kf = 0; kf < 2; kf++) {
                uint32_t afr[2][4];
                #pragma unroll
                for (int mi = 0; mi < 2; mi++) {
                    uint32_t addr = acur + a_ld_base[mi] +
                                    (((uint32_t)(kf * 2 + ksel) ^ a_swz[mi]) << 4);
                    LDMATRIX_X4(afr[mi][0], afr[mi][1], afr[mi][2], afr[mi][3], addr);
                }
                const uint32_t kchunk = ks * 4 + kf * 2 + bkh;
                #pragma unroll
                for (int nt = 0; nt < 4; nt++) {
                    const int lcls = wn * 64 + nt * 16 + bofs;
                    uint32_t b0, b1, b2, b3;
                    uint32_t addr = sb + SM_B + lcls * 512 +
                                    ((kchunk ^ (uint32_t)(lcls & 7)) << 4);
                    LDMATRIX_X4(b0, b1, b2, b3, addr);
                    #pragma unroll
                    for (int mi = 0; mi < 2; mi++) {
                        MMA16816(acc[mi][nt * 2 + 0], afr[mi][0], afr[mi][1], afr[mi][2], afr[mi][3], b0, b1);
                        MMA16816(acc[mi][nt * 2 + 1], afr[mi][0], afr[mi][1], afr[mi][2], afr[mi][3], b2, b3);
                    }
                }
            }

            if (have_next) {
                storeA(smA[(ks + 1) & 1]);
                BARG(barid);
            }
        }

        // ---- register epilogue: acc[mi][ni][h*2+e] <-> class wn*64+16t+2ni+e ----
        #pragma unroll
        for (int mi = 0; mi < 2; mi++) {
            #pragma unroll
            for (int h = 0; h < 2; h++) {
                const int pixel = mi * 16 + h * 8 + gq;
                const int4* lp = (const int4*)(labels +
                    (size_t)(pix0 + pixel) * M_CLS + wn * 64 + t * 16);
                int4 l0 = __ldg(lp);
                int4 l1 = __ldg(lp + 1);
                int4 l2 = __ldg(lp + 2);
                int4 l3 = __ldg(lp + 3);
                int l[16] = { l0.x, l0.y, l0.z, l0.w, l1.x, l1.y, l1.z, l1.w,
                              l2.x, l2.y, l2.z, l2.w, l3.x, l3.y, l3.z, l3.w };
                float sn = 0.0f, sp = 0.0f;
                #pragma unroll
                for (int ni = 0; ni < 8; ni++) {
                    #pragma unroll
                    for (int e = 0; e < 2; e++) {
                        int   lv = l[2 * ni + e];
                        float v  = acc[mi][ni][h * 2 + e] * SCALE_EX2;
                        float ev = ex2(lv ? -v : v);
                        if (lv) sp += ev; else sn += ev;
                    }
                }
                sn += __shfl_xor_sync(0xFFFFFFFFu, sn, 1);
                sn += __shfl_xor_sync(0xFFFFFFFFu, sn, 2);
                sp += __shfl_xor_sync(0xFFFFFFFFu, sp, 1);
                sp += __shfl_xor_sync(0xFFFFFFFFu, sp, 2);
                if (t == 0) {
                    red_sn[wn * 32 + pixel] = sn;
                    red_sp[wn * 32 + pixel] = sp;
                }
            }
        }
        BARG(barid);

        float th_loss = 0.0f, th_cnt = 0.0f;
        if (tig < 32) {    // warp 0 of the group (fully convergent)
            float tsn = red_sn[tig] + red_sn[32 + tig] + red_sn[64 + tig] + red_sn[96 + tig];
            float tsp = red_sp[tig] + red_sp[32 + tig] + red_sp[64 + tig] + red_sp[96 + tig];
            float loss = logf(tsn * tsp + 1.0f);
            th_loss = loss;
            th_cnt  = (loss != 0.0f) ? 1.0f : 0.0f;
            #pragma unroll
            for (int o = 16; o > 0; o >>= 1) {
                th_loss += __shfl_xor_sync(0xFFFFFFFFu, th_loss, o);
                th_cnt  += __shfl_xor_sync(0xFFFFFFFFu, th_cnt,  o);
            }
            if (lane == 0) { wpart[0] = th_loss; wpart[1] = th_cnt; }
        }
        BARG(barid);
        if (tig == 0) {
            acc_s += (double)wpart[0];
            acc_c += wpart[1];
        }

        fbase = fbase_next;
    }

    // ---- publish per-group totals; last finishing group reduces ----
    if (tig == 0) {
        g_sum[gid] = acc_s;
        g_cnt[gid] = acc_c;
        __threadfence();
        unsigned old = atomicAdd(&g_done, 1u);
        s_last[g] = (old == NGROUPS - 1);
    }
    BARG(barid);

    if (s_last[g]) {
        double* dsum = (double*)(smem + SM_FIN);          // 128 doubles
        float*  fcnt = (float*)(smem + SM_FIN + 1024);    // 128 floats
        double s = 0.0;
        float  c = 0.0f;
        #pragma unroll 1
        for (int i = tig; i < NGROUPS; i += 128) { s += g_sum[i]; c += g_cnt[i]; }
        dsum[tig] = s;
        fcnt[tig] = c;
        BARG(barid);
        for (int o = 64; o > 0; o >>= 1) {
            if (tig < o) { dsum[tig] += dsum[tig + o]; fcnt[tig] += fcnt[tig + o]; }
            BARG(barid);
        }
        if (tig == 0) {
            float cnt = fcnt[0];
            out[0] = (cnt == 0.0f) ? 0.0f : (float)(dsum[0] / (double)fmaxf(cnt, 1.0f));
            __threadfence();
            g_done = 0;   // reset for graph replay
        }
    }
}

extern "C" void kernel_launch(void* const* d_in, const int* in_sizes, int n_in,
                              void* d_out, int out_size)
{
    // metadata.txt order: feats (f32), queue (f32), labels (i32).
    // feats and labels have identical element counts — positional ID only.
    const float* feats  = (const float*)d_in[0];
    const float* queue  = (const float*)d_in[1];
    const int*   labels = (const int*)d_in[2];

    cudaFuncSetAttribute(pcl_main_kernel,
                         cudaFuncAttributeMaxDynamicSharedMemorySize, SMEM_BYTES);

    pcl_main_kernel<<<GRID, NTHREADS, SMEM_BYTES>>>(feats, queue, labels, (float*)d_out);
}